// round 5
// baseline (speedup 1.0000x reference)
#include <cuda_runtime.h>
#include <cstdint>

#define NROI 6144
#define NCLS 20
#define KSEL 615            // ceil(0.1 * 6144)
#define CSORT 1024
#define AW 20               // ceil(KSEL/32)
#define IOU_TH 0.25f
#define NCH 32              // g-chunks in kernel B
#define NSLAB 48            // NROI / 128

// ---- scratch (device globals; no allocations allowed) ----
__device__ unsigned char g_keep[NCLS * NROI];
__device__ int   g_cls[NROI];
__device__ float g_w[NROI];
__device__ int   g_list[NROI];
__device__ int   g_cnt;
__device__ unsigned long long g_part[NCH * NROI];   // packed partial maxes
__device__ unsigned int g_tick1;                    // kernel A ticket
__device__ unsigned int g_tick2[NSLAB];             // kernel B per-slab tickets

// ============================================================
// Kernel A: 20 blocks (one per class), 1024 threads.
//   label>0 classes: zero keep slice, build keys, radix-select
//   top-615, compact, hybrid bitonic sort, greedy NMS, publish keep.
//   LAST block (threadfence ticket) then runs the sequential
//   per-ROI class resolution (combine) and compacts gt list.
// ============================================================
__global__ void __launch_bounds__(1024, 1)
class_nms_kernel(const float* __restrict__ pc,
                 const float* __restrict__ pd,
                 const int* __restrict__ labels,
                 const float* __restrict__ iou) {
    __shared__ unsigned int skey[NROI];                 // 24KB
    __shared__ unsigned long long cand[CSORT];          // 8KB
    __shared__ unsigned int sh_hist[256];
    __shared__ unsigned int sh_wsum[8];
    __shared__ unsigned int sh_prefix, sh_k;
    __shared__ int sh_nc, sh_next;
    __shared__ unsigned int am[AW];
    __shared__ unsigned int s_old;
    __shared__ int s_label;
    __shared__ int s_labs[NCLS];
    __shared__ int s_cnt;

    const int c   = blockIdx.x;
    const int tid = threadIdx.x;
    const int nt  = blockDim.x;

    if (tid == 0) s_label = labels[c];
    __syncthreads();

    if (s_label > 0) {
        // zero this class's keep slice (stale from previous replay)
        for (int i = tid; i < NROI / 4; i += nt)
            ((unsigned int*)(g_keep + (size_t)c * NROI))[i] = 0u;

        // inverted float keys: ascending == prob descending
        for (int i = tid; i < NROI; i += nt) {
            float p = __ldg(&pc[i * (NCLS + 1) + c + 1]) *
                      __ldg(&pd[i * (NCLS + 1) + c + 1]);
            skey[i] = ~__float_as_uint(p);
        }
        if (tid == 0) { sh_prefix = 0; sh_k = KSEL; }
        __syncthreads();

        // ---- 4-pass MSB radix select with parallel bin scan ----
        for (int shift = 24; shift >= 0; shift -= 8) {
            if (tid < 256) sh_hist[tid] = 0;
            __syncthreads();
            const unsigned int prefix = sh_prefix;
            const unsigned int kcur   = sh_k;
            const unsigned int pmask  = (shift == 24) ? 0u : (0xFFFFFFFFu << (shift + 8));
            for (int i = tid; i < NROI; i += nt) {
                unsigned int key = skey[i];
                if ((key & pmask) == prefix)
                    atomicAdd(&sh_hist[(key >> shift) & 0xFF], 1u);
            }
            __syncthreads();
            unsigned int x = 0, hval = 0;
            if (tid < 256) {
                hval = sh_hist[tid];
                x = hval;
                #pragma unroll
                for (int off = 1; off < 32; off <<= 1) {
                    unsigned int y = __shfl_up_sync(0xFFFFFFFFu, x, off);
                    if ((tid & 31) >= off) x += y;
                }
                if ((tid & 31) == 31) sh_wsum[tid >> 5] = x;
            }
            __syncthreads();
            if (tid < 8) {
                unsigned int w = sh_wsum[tid];
                #pragma unroll
                for (int off = 1; off < 8; off <<= 1) {
                    unsigned int y = __shfl_up_sync(0xFFu, w, off);
                    if (tid >= off) w += y;
                }
                sh_wsum[tid] = w;
            }
            __syncthreads();
            if (tid < 256) {
                unsigned int incl = x + ((tid >= 32) ? sh_wsum[(tid >> 5) - 1] : 0u);
                unsigned int excl = incl - hval;
                if (incl >= kcur && excl < kcur) {
                    sh_prefix = prefix | ((unsigned int)tid << shift);
                    sh_k = kcur - excl;
                }
            }
            __syncthreads();
        }
        const unsigned int thr = sh_prefix;

        // ---- compact candidates ----
        if (tid == 0) sh_nc = 0;
        __syncthreads();
        for (int i = tid; i < NROI; i += nt) {
            unsigned int key = skey[i];
            if (key <= thr) {
                int pos = atomicAdd(&sh_nc, 1);
                if (pos < CSORT)
                    cand[pos] = ((unsigned long long)key << 32) | (unsigned int)i;
            }
        }
        __syncthreads();
        const int nc = sh_nc;
        if (tid >= nc && tid < CSORT) cand[tid] = 0xFFFFFFFFFFFFFFFFull;
        __syncthreads();

        // ---- bitonic sort 1024 u64: shfl for j<=16, smem for j>=32 ----
        {
            unsigned long long v = cand[tid];
            #pragma unroll
            for (unsigned int k = 2; k <= 32; k <<= 1) {
                bool asc = ((tid & k) == 0);
                #pragma unroll
                for (unsigned int j = k >> 1; j >= 1; j >>= 1) {
                    unsigned long long o = __shfl_xor_sync(0xFFFFFFFFu, v, j);
                    bool keepmin = (((tid & j) == 0) == asc);
                    v = (keepmin == (v <= o)) ? v : o;
                }
            }
            cand[tid] = v;
        }
        __syncthreads();
        for (unsigned int k = 64; k <= CSORT; k <<= 1) {
            for (unsigned int j = k >> 1; j >= 32; j >>= 1) {
                unsigned int i = tid, ixj = i ^ j;
                if (ixj > i) {
                    unsigned long long a = cand[i], b = cand[ixj];
                    bool asc = ((i & k) == 0);
                    if ((a > b) == asc) { cand[i] = b; cand[ixj] = a; }
                }
                __syncthreads();
            }
            {
                unsigned long long v = cand[tid];
                bool asc = ((tid & k) == 0);
                #pragma unroll
                for (unsigned int j = 16; j >= 1; j >>= 1) {
                    unsigned long long o = __shfl_xor_sync(0xFFFFFFFFu, v, j);
                    bool keepmin = (((tid & j) == 0) == asc);
                    v = (keepmin == (v <= o)) ? v : o;
                }
                cand[tid] = v;
            }
            __syncthreads();
        }

        // ---- greedy NMS with alive bitmask + skip scan ----
        for (int w = tid; w < AW; w += nt) am[w] = 0xFFFFFFFFu;
        if (tid == 0) {
            am[AW - 1] = (1u << (KSEL - 32 * (AW - 1))) - 1;
            sh_next = 0;
        }
        __syncthreads();

        while (true) {
            const int i = sh_next;
            if (i >= KSEL) break;
            const int oi = (unsigned int)cand[i];
            if (tid == 0) g_keep[(size_t)c * NROI + oi] = 1;
            const int j = i + 1 + tid;
            if (j < KSEL) {
                const int oj = (unsigned int)cand[j];
                float v = iou[(size_t)oi * NROI + oj];
                if (v >= IOU_TH) atomicAnd(&am[j >> 5], ~(1u << (j & 31)));
            }
            __syncthreads();
            if (tid == 0) {
                int nx = KSEL;
                int start = i + 1;
                int w = start >> 5;
                unsigned int m = (w < AW) ? (am[w] & (0xFFFFFFFFu << (start & 31))) : 0u;
                while (true) {
                    if (m) { nx = (w << 5) + __ffs(m) - 1; break; }
                    if (++w >= AW) break;
                    m = am[w];
                }
                sh_next = nx;
            }
            __syncthreads();
        }
    }

    // ---- ticket: last block runs combine ----
    __syncthreads();
    if (tid == 0) {
        __threadfence();
        s_old = atomicAdd(&g_tick1, 1u);
    }
    __syncthreads();
    if (s_old == NCLS - 1) {
        __threadfence();
        if (tid < NCLS) s_labs[tid] = labels[tid];
        if (tid == 0) s_cnt = 0;
        __syncthreads();
        for (int i = tid; i < NROI; i += nt) {
            float w = -1.0f;
            int cls = 0;
            #pragma unroll
            for (int cc = 0; cc < NCLS; ++cc) {
                if (s_labs[cc] > 0 && g_keep[(size_t)cc * NROI + i]) {
                    float p = __ldg(&pc[i * (NCLS + 1) + cc + 1]) *
                              __ldg(&pd[i * (NCLS + 1) + cc + 1]);
                    if (p > w) { w = p; cls = cc + 1; }
                }
            }
            g_cls[i] = cls;
            g_w[i]   = w;
            if (cls > 0) {
                int pos = atomicAdd(&s_cnt, 1);
                g_list[pos] = i;
            }
        }
        __syncthreads();
        if (tid == 0) { g_cnt = s_cnt; g_tick1 = 0; }
    }
}

// ============================================================
// Kernel B: grid (48 slabs x 32 g-chunks), 128 threads.
//   each block: max over its g-chunk for its 128 ROIs -> g_part
//   (packed (v_bits<<32)|(NROI-j): exact smallest-j tie-break)
//   per-slab LAST block reduces 32 partials and emits outputs.
// ============================================================
__device__ __forceinline__ void upd(float& mv, int& mj, float v, int j) {
    if (v > mv || (v == mv && j < mj)) { mv = v; mj = j; }
}

__global__ void __launch_bounds__(128)
partial_final_kernel(const float* __restrict__ iou, float* __restrict__ out) {
    __shared__ unsigned int s_old;
    __shared__ int   s_lab[128];
    __shared__ float s_v[128];
    __shared__ float s_w[128];

    const int bi = blockIdx.x;            // slab
    const int ch = blockIdx.y;            // g-chunk
    const int t  = threadIdx.x;
    const int i  = bi * 128 + t;

    const int G   = g_cnt;
    const int len = (G + NCH - 1) / NCH;
    const int g0  = ch * len;
    const int g1  = min(G, g0 + len);

    unsigned long long key = 0ull;
    if (g0 < g1) {
        float mv0 = -1.0f, mv1 = -1.0f, mv2 = -1.0f, mv3 = -1.0f;
        int   mj0 = 0,     mj1 = 0,     mj2 = 0,     mj3 = 0;
        int g = g0;
        for (; g + 4 <= g1; g += 4) {
            int j0 = __ldg(&g_list[g]),     j1 = __ldg(&g_list[g + 1]);
            int j2 = __ldg(&g_list[g + 2]), j3 = __ldg(&g_list[g + 3]);
            float v0 = iou[(size_t)j0 * NROI + i];
            float v1 = iou[(size_t)j1 * NROI + i];
            float v2 = iou[(size_t)j2 * NROI + i];
            float v3 = iou[(size_t)j3 * NROI + i];
            upd(mv0, mj0, v0, j0); upd(mv1, mj1, v1, j1);
            upd(mv2, mj2, v2, j2); upd(mv3, mj3, v3, j3);
        }
        for (; g < g1; ++g) {
            int j0 = __ldg(&g_list[g]);
            upd(mv0, mj0, iou[(size_t)j0 * NROI + i], j0);
        }
        upd(mv0, mj0, mv1, mj1);
        upd(mv2, mj2, mv3, mj3);
        upd(mv0, mj0, mv2, mj2);
        key = ((unsigned long long)__float_as_uint(mv0) << 32) |
              (unsigned long long)(unsigned int)(NROI - mj0);
    }
    g_part[(size_t)ch * NROI + i] = key;

    __threadfence();
    if (t == 0) s_old = atomicAdd(&g_tick2[bi], 1u);
    __syncthreads();
    if (s_old != NCH - 1) return;

    __threadfence();
    // reduce 32 partials for my ROI
    unsigned long long best = 0ull;
    #pragma unroll
    for (int c2 = 0; c2 < NCH; ++c2) {
        unsigned long long k2 = g_part[(size_t)c2 * NROI + i];
        if (k2 > best) best = k2;
    }
    const unsigned int jf = (unsigned int)(best & 0xFFFFFFFFull);
    const float maxv = __uint_as_float((unsigned int)(best >> 32));
    const int   maxj = (jf == 0) ? 0 : (NROI - (int)jf);

    const int   cls = g_cls[maxj];
    const float lw  = g_w[maxj];
    const bool ignore = (maxv == 0.0f);
    const bool bg     = (maxv < IOU_TH) && !ignore;
    s_lab[t] = ignore ? -1 : (bg ? 0 : cls);
    s_v[t]   = maxv;
    s_w[t]   = ignore ? 0.0f : lw;
    __syncthreads();

    // coalesced emit of the 128x21 one-hot rows
    for (int e = t; e < 128 * (NCLS + 1); e += 128) {
        int il = e / (NCLS + 1);
        int k  = e - il * (NCLS + 1);
        out[(size_t)(bi * 128 + il) * (NCLS + 1) + k] = (k == s_lab[il]) ? 1.0f : 0.0f;
    }
    out[(size_t)NROI * (NCLS + 1) + i]        = s_v[t];
    out[(size_t)NROI * (NCLS + 1) + NROI + i] = s_w[t];

    if (t == 0) g_tick2[bi] = 0;   // reset for next replay
}

extern "C" void kernel_launch(void* const* d_in, const int* in_sizes, int n_in,
                              void* d_out, int out_size) {
    const float* pc     = (const float*)d_in[0];
    const float* pd     = (const float*)d_in[1];
    // d_in[2] = rois (unused)
    const int*   labels = (const int*)d_in[3];
    const float* iou    = (const float*)d_in[4];
    float* out = (float*)d_out;

    class_nms_kernel<<<NCLS, 1024>>>(pc, pd, labels, iou);
    partial_final_kernel<<<dim3(NSLAB, NCH), 128>>>(iou, out);
}

// round 6
// speedup vs baseline: 1.5431x; 1.5431x over previous
#include <cuda_runtime.h>
#include <cstdint>

#define NROI 6144
#define NCLS 20
#define KSEL 615            // ceil(0.1 * 6144)
#define CSORT 1024
#define AW 20               // ceil(KSEL/32)
#define IOU_TH 0.25f
#define NCH 32              // g-chunks in partial kernel

// ---- scratch (device globals; no allocations allowed) ----
__device__ unsigned long long g_cw[NROI];    // packed (prob_bits<<32)|(NCLS-c); 0 = none
__device__ unsigned long long g_best[NROI];  // packed (v_bits<<32)|(NROI-j)
__device__ int g_list[NROI];                 // kept boxes (dups across classes OK)
__device__ int g_cnt;

// ============================================================
// Kernel 0: reset state for this launch
// ============================================================
__global__ void init_kernel() {
    int i = blockIdx.x * blockDim.x + threadIdx.x;
    if (i < NROI) { g_cw[i] = 0ull; g_best[i] = 0ull; }
    if (i == 0) g_cnt = 0;
}

// ============================================================
// Kernel 1: one block per class; label==0 classes exit.
//   radix-select top-615 -> compact -> hybrid bitonic sort ->
//   greedy NMS; kept boxes: append to g_list + atomicMax publish
//   of (prob, class) (exact sequential-update semantics:
//   strictly-greater prob wins; equal prob -> smaller c wins).
// ============================================================
__global__ void __launch_bounds__(1024, 1)
class_nms_kernel(const float* __restrict__ pc,
                 const float* __restrict__ pd,
                 const int* __restrict__ labels,
                 const float* __restrict__ iou) {
    __shared__ unsigned int skey[NROI];                 // 24KB
    __shared__ unsigned long long cand[CSORT];          // 8KB
    __shared__ unsigned int sh_hist[256];
    __shared__ unsigned int sh_wsum[8];
    __shared__ unsigned int sh_prefix, sh_k;
    __shared__ int sh_nc, sh_next;
    __shared__ unsigned int am[AW];

    const int c   = blockIdx.x;
    const int tid = threadIdx.x;
    const int nt  = blockDim.x;

    if (labels[c] == 0) return;

    // inverted float keys: ascending == prob descending
    for (int i = tid; i < NROI; i += nt) {
        float p = __ldg(&pc[i * (NCLS + 1) + c + 1]) *
                  __ldg(&pd[i * (NCLS + 1) + c + 1]);
        skey[i] = ~__float_as_uint(p);
    }
    if (tid == 0) { sh_prefix = 0; sh_k = KSEL; }
    __syncthreads();

    // ---- 4-pass MSB radix select with parallel bin scan ----
    for (int shift = 24; shift >= 0; shift -= 8) {
        if (tid < 256) sh_hist[tid] = 0;
        __syncthreads();
        const unsigned int prefix = sh_prefix;
        const unsigned int kcur   = sh_k;
        const unsigned int pmask  = (shift == 24) ? 0u : (0xFFFFFFFFu << (shift + 8));
        for (int i = tid; i < NROI; i += nt) {
            unsigned int key = skey[i];
            if ((key & pmask) == prefix)
                atomicAdd(&sh_hist[(key >> shift) & 0xFF], 1u);
        }
        __syncthreads();
        unsigned int x = 0, hval = 0;
        if (tid < 256) {
            hval = sh_hist[tid];
            x = hval;
            #pragma unroll
            for (int off = 1; off < 32; off <<= 1) {
                unsigned int y = __shfl_up_sync(0xFFFFFFFFu, x, off);
                if ((tid & 31) >= off) x += y;
            }
            if ((tid & 31) == 31) sh_wsum[tid >> 5] = x;
        }
        __syncthreads();
        if (tid < 8) {
            unsigned int w = sh_wsum[tid];
            #pragma unroll
            for (int off = 1; off < 8; off <<= 1) {
                unsigned int y = __shfl_up_sync(0xFFu, w, off);
                if (tid >= off) w += y;
            }
            sh_wsum[tid] = w;
        }
        __syncthreads();
        if (tid < 256) {
            unsigned int incl = x + ((tid >= 32) ? sh_wsum[(tid >> 5) - 1] : 0u);
            unsigned int excl = incl - hval;
            if (incl >= kcur && excl < kcur) {
                sh_prefix = prefix | ((unsigned int)tid << shift);
                sh_k = kcur - excl;
            }
        }
        __syncthreads();
    }
    const unsigned int thr = sh_prefix;

    // ---- compact candidates (key <= thr) ----
    if (tid == 0) sh_nc = 0;
    __syncthreads();
    for (int i = tid; i < NROI; i += nt) {
        unsigned int key = skey[i];
        if (key <= thr) {
            int pos = atomicAdd(&sh_nc, 1);
            if (pos < CSORT)
                cand[pos] = ((unsigned long long)key << 32) | (unsigned int)i;
        }
    }
    __syncthreads();
    const int nc = sh_nc;
    if (tid >= nc && tid < CSORT) cand[tid] = 0xFFFFFFFFFFFFFFFFull;
    __syncthreads();

    // ---- bitonic sort 1024 u64: shfl for j<=16, smem for j>=32 ----
    {
        unsigned long long v = cand[tid];
        #pragma unroll
        for (unsigned int k = 2; k <= 32; k <<= 1) {
            bool asc = ((tid & k) == 0);
            #pragma unroll
            for (unsigned int j = k >> 1; j >= 1; j >>= 1) {
                unsigned long long o = __shfl_xor_sync(0xFFFFFFFFu, v, j);
                bool keepmin = (((tid & j) == 0) == asc);
                v = (keepmin == (v <= o)) ? v : o;
            }
        }
        cand[tid] = v;
    }
    __syncthreads();
    for (unsigned int k = 64; k <= CSORT; k <<= 1) {
        for (unsigned int j = k >> 1; j >= 32; j >>= 1) {
            unsigned int i = tid, ixj = i ^ j;
            if (ixj > i) {
                unsigned long long a = cand[i], b = cand[ixj];
                bool asc = ((i & k) == 0);
                if ((a > b) == asc) { cand[i] = b; cand[ixj] = a; }
            }
            __syncthreads();
        }
        {
            unsigned long long v = cand[tid];
            bool asc = ((tid & k) == 0);
            #pragma unroll
            for (unsigned int j = 16; j >= 1; j >>= 1) {
                unsigned long long o = __shfl_xor_sync(0xFFFFFFFFu, v, j);
                bool keepmin = (((tid & j) == 0) == asc);
                v = (keepmin == (v <= o)) ? v : o;
            }
            cand[tid] = v;
        }
        __syncthreads();
    }

    // ---- greedy NMS; publish kept boxes ----
    for (int w = tid; w < AW; w += nt) am[w] = 0xFFFFFFFFu;
    if (tid == 0) {
        am[AW - 1] = (1u << (KSEL - 32 * (AW - 1))) - 1;
        sh_next = 0;
    }
    __syncthreads();

    while (true) {
        const int i = sh_next;
        if (i >= KSEL) break;
        const unsigned long long ci = cand[i];
        const int oi = (unsigned int)ci;
        if (tid == 0) {
            unsigned int pbits = ~(unsigned int)(ci >> 32);
            atomicMax(&g_cw[oi],
                      ((unsigned long long)pbits << 32) |
                      (unsigned long long)(unsigned int)(NCLS - c));
            int pos = atomicAdd(&g_cnt, 1);
            g_list[pos] = oi;                          // dups across classes are OK
        }
        const int j = i + 1 + tid;
        if (j < KSEL) {
            const int oj = (unsigned int)cand[j];
            float v = iou[(size_t)oi * NROI + oj];
            if (v >= IOU_TH) atomicAnd(&am[j >> 5], ~(1u << (j & 31)));
        }
        __syncthreads();
        if (tid == 0) {
            int nx = KSEL;
            int start = i + 1;
            int w = start >> 5;
            unsigned int m = (w < AW) ? (am[w] & (0xFFFFFFFFu << (start & 31))) : 0u;
            while (true) {
                if (m) { nx = (w << 5) + __ffs(m) - 1; break; }
                if (++w >= AW) break;
                m = am[w];
            }
            sh_next = nx;
        }
        __syncthreads();
    }
}

// ============================================================
// Kernel 2: partial masked max; grid (24, NCH) x 256 threads.
// Each thread: ~ceil(G/NCH) independent gathers -> one latency
// round; merge via packed atomicMax (exact smallest-j tie-break).
// ============================================================
__device__ __forceinline__ void upd(float& mv, int& mj, float v, int j) {
    if (v > mv || (v == mv && j < mj)) { mv = v; mj = j; }
}

__global__ void __launch_bounds__(256)
partial_kernel(const float* __restrict__ iou) {
    const int i = blockIdx.x * 256 + threadIdx.x;
    const int G = g_cnt;
    const int len = (G + NCH - 1) / NCH;
    const int g0 = blockIdx.y * len;
    const int g1 = min(G, g0 + len);
    if (g0 >= g1) return;

    float mv0 = -1.0f, mv1 = -1.0f, mv2 = -1.0f, mv3 = -1.0f;
    int   mj0 = 0,     mj1 = 0,     mj2 = 0,     mj3 = 0;
    int g = g0;
    for (; g + 4 <= g1; g += 4) {
        int j0 = __ldg(&g_list[g]),     j1 = __ldg(&g_list[g + 1]);
        int j2 = __ldg(&g_list[g + 2]), j3 = __ldg(&g_list[g + 3]);
        float v0 = iou[(size_t)j0 * NROI + i];
        float v1 = iou[(size_t)j1 * NROI + i];
        float v2 = iou[(size_t)j2 * NROI + i];
        float v3 = iou[(size_t)j3 * NROI + i];
        upd(mv0, mj0, v0, j0); upd(mv1, mj1, v1, j1);
        upd(mv2, mj2, v2, j2); upd(mv3, mj3, v3, j3);
    }
    for (; g < g1; ++g) {
        int j0 = __ldg(&g_list[g]);
        upd(mv0, mj0, iou[(size_t)j0 * NROI + i], j0);
    }
    upd(mv0, mj0, mv1, mj1);
    upd(mv2, mj2, mv3, mj3);
    upd(mv0, mj0, mv2, mj2);

    unsigned long long key =
        ((unsigned long long)__float_as_uint(mv0) << 32) |
        (unsigned long long)(unsigned int)(NROI - mj0);
    atomicMax(&g_best[i], key);
}

// ============================================================
// Kernel 3: unpack + coalesced emit
// ============================================================
__global__ void __launch_bounds__(256)
final_out_kernel(float* __restrict__ out) {
    __shared__ int   s_lab[256];
    __shared__ float s_v[256];
    __shared__ float s_w[256];
    const int t = threadIdx.x;
    const int i = blockIdx.x * 256 + t;

    unsigned long long b = g_best[i];
    const unsigned int jf = (unsigned int)(b & 0xFFFFFFFFull);
    const float maxv = __uint_as_float((unsigned int)(b >> 32));
    const int   maxj = (jf == 0) ? 0 : (NROI - (int)jf);

    unsigned long long cw = g_cw[maxj];
    const int   cls = (int)(NCLS + 1) - (int)(unsigned int)(cw & 0xFFFFFFFFull); // c+1
    const float lw  = __uint_as_float((unsigned int)(cw >> 32));

    const bool ignore = (maxv == 0.0f);
    const bool bg     = (maxv < IOU_TH) && !ignore;
    s_lab[t] = ignore ? -1 : (bg ? 0 : cls);
    s_v[t]   = maxv;
    s_w[t]   = ignore ? 0.0f : lw;
    __syncthreads();

    // coalesced one-hot emit: 256 rows x 21 cols
    const size_t base = (size_t)blockIdx.x * 256 * (NCLS + 1);
    for (int e = t; e < 256 * (NCLS + 1); e += 256) {
        int il = e / (NCLS + 1);
        int k  = e - il * (NCLS + 1);
        out[base + e] = (k == s_lab[il]) ? 1.0f : 0.0f;
    }
    out[(size_t)NROI * (NCLS + 1) + i]        = s_v[t];
    out[(size_t)NROI * (NCLS + 1) + NROI + i] = s_w[t];
}

extern "C" void kernel_launch(void* const* d_in, const int* in_sizes, int n_in,
                              void* d_out, int out_size) {
    const float* pc     = (const float*)d_in[0];
    const float* pd     = (const float*)d_in[1];
    // d_in[2] = rois (unused)
    const int*   labels = (const int*)d_in[3];
    const float* iou    = (const float*)d_in[4];
    float* out = (float*)d_out;

    init_kernel<<<6, 1024>>>();
    class_nms_kernel<<<NCLS, 1024>>>(pc, pd, labels, iou);
    partial_kernel<<<dim3(NROI / 256, NCH), 256>>>(iou);
    final_out_kernel<<<NROI / 256, 256>>>(out);
}

// round 7
// speedup vs baseline: 1.8104x; 1.1732x over previous
#include <cuda_runtime.h>
#include <cstdint>

#define NROI 6144
#define NCLS 20
#define KSEL 615            // ceil(0.1 * 6144)
#define CSORT 1024
#define AW 20               // ceil(KSEL/32)
#define IOU_TH 0.25f
#define KPT 6               // keys per thread (6144/1024)
#define LMAX 16384          // worst-case kept list (20*615 < 16384)
#define LCACHE 2048         // smem-cached list entries (typical G ~ 150)

// ---- scratch (device globals; zero-initialized at load) ----
__device__ int g_list[LMAX];                 // kept ROI indices (dups across classes OK)
__device__ unsigned long long g_lv[LMAX];    // packed (prob_bits<<32)|(NCLS-c)
__device__ int g_cnt;                        // reset by kernel C for next replay

// ============================================================
// Kernel A: one block per class; label==0 classes exit.
//   register-resident keys -> 4-pass radix select (top-615) ->
//   compact -> hybrid bitonic sort -> greedy NMS -> publish
//   kept (idx, prob, class) to compact list.
// ============================================================
__global__ void __launch_bounds__(1024, 1)
class_nms_kernel(const float* __restrict__ pc,
                 const float* __restrict__ pd,
                 const int* __restrict__ labels,
                 const float* __restrict__ iou) {
    __shared__ unsigned long long cand[CSORT];          // 8KB
    __shared__ unsigned int sh_hist[256];
    __shared__ unsigned int sh_wsum[8];
    __shared__ unsigned int sh_prefix, sh_k;
    __shared__ int sh_nc, sh_next;
    __shared__ unsigned int am[AW];

    const int c   = blockIdx.x;
    const int tid = threadIdx.x;
    const int nt  = blockDim.x;

    if (labels[c] == 0) return;

    // register-resident inverted keys: ascending == prob descending
    unsigned int key[KPT];
    #pragma unroll
    for (int r = 0; r < KPT; ++r) {
        int i = tid + r * 1024;
        float p = __ldg(&pc[i * (NCLS + 1) + c + 1]) *
                  __ldg(&pd[i * (NCLS + 1) + c + 1]);
        key[r] = ~__float_as_uint(p);
    }
    if (tid == 0) { sh_prefix = 0; sh_k = KSEL; }
    __syncthreads();

    // ---- 4-pass MSB radix select with parallel bin scan ----
    for (int shift = 24; shift >= 0; shift -= 8) {
        if (tid < 256) sh_hist[tid] = 0;
        __syncthreads();
        const unsigned int prefix = sh_prefix;
        const unsigned int kcur   = sh_k;
        const unsigned int pmask  = (shift == 24) ? 0u : (0xFFFFFFFFu << (shift + 8));
        #pragma unroll
        for (int r = 0; r < KPT; ++r)
            if ((key[r] & pmask) == prefix)
                atomicAdd(&sh_hist[(key[r] >> shift) & 0xFF], 1u);
        __syncthreads();
        unsigned int x = 0, hval = 0;
        if (tid < 256) {
            hval = sh_hist[tid];
            x = hval;
            #pragma unroll
            for (int off = 1; off < 32; off <<= 1) {
                unsigned int y = __shfl_up_sync(0xFFFFFFFFu, x, off);
                if ((tid & 31) >= off) x += y;
            }
            if ((tid & 31) == 31) sh_wsum[tid >> 5] = x;
        }
        __syncthreads();
        if (tid < 8) {
            unsigned int w = sh_wsum[tid];
            #pragma unroll
            for (int off = 1; off < 8; off <<= 1) {
                unsigned int y = __shfl_up_sync(0xFFu, w, off);
                if (tid >= off) w += y;
            }
            sh_wsum[tid] = w;
        }
        __syncthreads();
        if (tid < 256) {
            unsigned int incl = x + ((tid >= 32) ? sh_wsum[(tid >> 5) - 1] : 0u);
            unsigned int excl = incl - hval;
            if (incl >= kcur && excl < kcur) {
                sh_prefix = prefix | ((unsigned int)tid << shift);
                sh_k = kcur - excl;
            }
        }
        __syncthreads();
    }
    const unsigned int thr = sh_prefix;

    // ---- compact candidates (key <= thr) ----
    if (tid == 0) sh_nc = 0;
    __syncthreads();
    #pragma unroll
    for (int r = 0; r < KPT; ++r) {
        if (key[r] <= thr) {
            int pos = atomicAdd(&sh_nc, 1);
            if (pos < CSORT)
                cand[pos] = ((unsigned long long)key[r] << 32) |
                            (unsigned int)(tid + r * 1024);
        }
    }
    __syncthreads();
    const int nc = sh_nc;
    if (tid >= nc && tid < CSORT) cand[tid] = 0xFFFFFFFFFFFFFFFFull;
    __syncthreads();

    // ---- bitonic sort 1024 u64: shfl for j<=16, smem for j>=32 ----
    {
        unsigned long long v = cand[tid];
        #pragma unroll
        for (unsigned int k = 2; k <= 32; k <<= 1) {
            bool asc = ((tid & k) == 0);
            #pragma unroll
            for (unsigned int j = k >> 1; j >= 1; j >>= 1) {
                unsigned long long o = __shfl_xor_sync(0xFFFFFFFFu, v, j);
                bool keepmin = (((tid & j) == 0) == asc);
                v = (keepmin == (v <= o)) ? v : o;
            }
        }
        cand[tid] = v;
    }
    __syncthreads();
    for (unsigned int k = 64; k <= CSORT; k <<= 1) {
        for (unsigned int j = k >> 1; j >= 32; j >>= 1) {
            unsigned int i = tid, ixj = i ^ j;
            if (ixj > i) {
                unsigned long long a = cand[i], b = cand[ixj];
                bool asc = ((i & k) == 0);
                if ((a > b) == asc) { cand[i] = b; cand[ixj] = a; }
            }
            __syncthreads();
        }
        {
            unsigned long long v = cand[tid];
            bool asc = ((tid & k) == 0);
            #pragma unroll
            for (unsigned int j = 16; j >= 1; j >>= 1) {
                unsigned long long o = __shfl_xor_sync(0xFFFFFFFFu, v, j);
                bool keepmin = (((tid & j) == 0) == asc);
                v = (keepmin == (v <= o)) ? v : o;
            }
            cand[tid] = v;
        }
        __syncthreads();
    }

    // ---- greedy NMS; publish kept boxes to compact list ----
    for (int w = tid; w < AW; w += nt) am[w] = 0xFFFFFFFFu;
    if (tid == 0) {
        am[AW - 1] = (1u << (KSEL - 32 * (AW - 1))) - 1;
        sh_next = 0;
    }
    __syncthreads();

    while (true) {
        const int i = sh_next;
        if (i >= KSEL) break;
        const unsigned long long ci = cand[i];
        const int oi = (unsigned int)ci;
        if (tid == 0) {
            unsigned int pbits = ~(unsigned int)(ci >> 32);
            int pos = atomicAdd(&g_cnt, 1);
            g_list[pos] = oi;
            g_lv[pos] = ((unsigned long long)pbits << 32) |
                        (unsigned long long)(unsigned int)(NCLS - c);
        }
        const int j = i + 1 + tid;
        if (j < KSEL) {
            const int oj = (unsigned int)cand[j];
            float v = iou[(size_t)oi * NROI + oj];
            if (v >= IOU_TH) atomicAnd(&am[j >> 5], ~(1u << (j & 31)));
        }
        __syncthreads();
        if (tid == 0) {
            int nx = KSEL;
            int start = i + 1;
            int w = start >> 5;
            unsigned int m = (w < AW) ? (am[w] & (0xFFFFFFFFu << (start & 31))) : 0u;
            while (true) {
                if (m) { nx = (w << 5) + __ffs(m) - 1; break; }
                if (++w >= AW) break;
                m = am[w];
            }
            sh_next = nx;
        }
        __syncthreads();
    }
}

// ============================================================
// Kernel C: fused partial-max + class resolution + emit.
// grid 24 x 1024: slab of 256 ROIs; thread (ch = t>>8, il = t&255)
// handles ROI i = bi*256+il over g-chunk ch (4 chunks, 8-way ILP).
// smem class-table rebuilt per block via atomicMax (exact
// sequential-update semantics). Block 0 resets g_cnt at the end.
// ============================================================
__device__ __forceinline__ void upd(float& mv, int& mj, float v, int j) {
    if (v > mv || (v == mv && j < mj)) { mv = v; mj = j; }
}

__global__ void __launch_bounds__(1024, 1)
fused_final_kernel(const float* __restrict__ iou, float* __restrict__ out) {
    extern __shared__ unsigned long long dyn[];
    unsigned long long* s_cw   = dyn;                   // NROI u64 = 48KB
    unsigned long long* s_part = dyn + NROI;            // 1024 u64 = 8KB
    int*   s_list = (int*)(s_part + 1024);              // LCACHE ints = 8KB
    int*   s_lab  = s_list + LCACHE;                    // 256
    float* s_v    = (float*)(s_lab + 256);              // 256
    float* s_w    = s_v + 256;                          // 256

    const int t  = threadIdx.x;
    const int bi = blockIdx.x;
    const int il = t & 255;
    const int ch = t >> 8;
    const int i  = bi * 256 + il;

    const int G = g_cnt;

    // zero class table, then scatter-max the kept list into it
    for (int e = t; e < NROI; e += 1024) s_cw[e] = 0ull;
    __syncthreads();
    for (int e = t; e < G; e += 1024) {
        int oi = g_list[e];
        if (e < LCACHE) s_list[e] = oi;
        atomicMax(&s_cw[oi], g_lv[e]);
    }
    __syncthreads();

    // gather phase: chunk ch of [0,G), 8-way ILP
    const int len = (G + 3) >> 2;
    const int g0 = ch * len;
    const int g1 = min(G, g0 + len);

    unsigned long long pkey = 0ull;
    if (g0 < g1) {
        float mv[8]; int mj[8];
        #pragma unroll
        for (int r = 0; r < 8; ++r) { mv[r] = -1.0f; mj[r] = 0; }
        if (g1 <= LCACHE) {
            int g = g0;
            for (; g + 8 <= g1; g += 8) {
                #pragma unroll
                for (int r = 0; r < 8; ++r) {
                    int j = s_list[g + r];
                    upd(mv[r], mj[r], iou[(size_t)j * NROI + i], j);
                }
            }
            for (; g < g1; ++g) {
                int j = s_list[g];
                upd(mv[0], mj[0], iou[(size_t)j * NROI + i], j);
            }
        } else {
            int g = g0;
            for (; g + 8 <= g1; g += 8) {
                #pragma unroll
                for (int r = 0; r < 8; ++r) {
                    int j = __ldg(&g_list[g + r]);
                    upd(mv[r], mj[r], iou[(size_t)j * NROI + i], j);
                }
            }
            for (; g < g1; ++g) {
                int j = __ldg(&g_list[g]);
                upd(mv[0], mj[0], iou[(size_t)j * NROI + i], j);
            }
        }
        #pragma unroll
        for (int r = 4; r >= 1; r >>= 1)
            #pragma unroll
            for (int r2 = 0; r2 < 8; ++r2)
                if (r2 < r) upd(mv[r2], mj[r2], mv[r2 + r], mj[r2 + r]);
        pkey = ((unsigned long long)__float_as_uint(mv[0]) << 32) |
               (unsigned long long)(unsigned int)(NROI - mj[0]);
    }
    s_part[t] = pkey;
    __syncthreads();

    // reduce 4 chunks + class lookup + staging (threads 0..255)
    if (t < 256) {
        unsigned long long best = s_part[t];
        unsigned long long b1 = s_part[t + 256];
        unsigned long long b2 = s_part[t + 512];
        unsigned long long b3 = s_part[t + 768];
        if (b1 > best) best = b1;
        if (b2 > best) best = b2;
        if (b3 > best) best = b3;

        const float maxv = __uint_as_float((unsigned int)(best >> 32));
        const int   maxj = NROI - (int)(unsigned int)(best & 0xFFFFFFFFull);

        const unsigned long long cw = s_cw[maxj];
        const int   cls = (int)(NCLS + 1) - (int)(unsigned int)(cw & 0xFFFFFFFFull);
        const float lw  = __uint_as_float((unsigned int)(cw >> 32));

        const bool ignore = (maxv == 0.0f);
        const bool bg     = (maxv < IOU_TH) && !ignore;
        s_lab[t] = ignore ? -1 : (bg ? 0 : cls);
        s_v[t]   = maxv;
        s_w[t]   = ignore ? 0.0f : lw;
    }
    __syncthreads();

    // coalesced emit: 256 rows x 21 one-hot
    const size_t base = (size_t)bi * 256 * (NCLS + 1);
    for (int e = t; e < 256 * (NCLS + 1); e += 1024) {
        int row = e / (NCLS + 1);
        int k   = e - row * (NCLS + 1);
        out[base + e] = (k == s_lab[row]) ? 1.0f : 0.0f;
    }
    if (t < 256) {
        out[(size_t)NROI * (NCLS + 1) + i]        = s_v[t];
        out[(size_t)NROI * (NCLS + 1) + NROI + i] = s_w[t];
    }

    // reset for next graph replay (all blocks read g_cnt in their first
    // instructions while co-resident in wave 1; this store is ~10k cycles later)
    if (bi == 0 && t == 0) g_cnt = 0;
}

extern "C" void kernel_launch(void* const* d_in, const int* in_sizes, int n_in,
                              void* d_out, int out_size) {
    const float* pc     = (const float*)d_in[0];
    const float* pd     = (const float*)d_in[1];
    // d_in[2] = rois (unused)
    const int*   labels = (const int*)d_in[3];
    const float* iou    = (const float*)d_in[4];
    float* out = (float*)d_out;

    const int dsmem = NROI * 8 + 1024 * 8 + LCACHE * 4 + 256 * 12;
    cudaFuncSetAttribute(fused_final_kernel,
                         cudaFuncAttributeMaxDynamicSharedMemorySize, dsmem);

    class_nms_kernel<<<NCLS, 1024>>>(pc, pd, labels, iou);
    fused_final_kernel<<<NROI / 256, 1024, dsmem>>>(iou, out);
}